// round 10
// baseline (speedup 1.0000x reference)
#include <cuda_runtime.h>
#include <cuda_fp16.h>
#include <math.h>
#include <stdint.h>

// Problem constants (fixed by setup_inputs)
namespace {
constexpr int BB = 2;
constexpr int LL = 1024;
constexpr int CC = 1024;
constexpr int HH = 8;
constexpr int DD = 128;   // CC / HH
constexpr int SS = 32;    // sample taps
constexpr int KK = 64;    // kernel taps
constexpr int BL = BB * LL;           // 2048
constexpr int HK = HH * KK;           // 512
constexpr int WPITCH = 1028;          // wave_w smem pitch (floats)
}

// ---------------- scratch (static device globals; no runtime allocation) ----
__device__ float  g_freq [BL * HH];
__device__ float  g_phase[BL * HH];
__device__ float  g_kmat [BL * HK];       // 4 MB (fp32 accum out of f16 GEMM)
__device__ __half g_yh   [BL * CC];       // 4 MB y (fp16)
__device__ __half g_xh   [BL * CC];       // 4 MB x (fp16): gather + kmat A
__device__ __half g_wkh  [HK * CC];       // kernel_w fp16 [N][K]
__device__ __half g_woh  [CC * CC];       // out_w fp16 [N][K]

// ---------------- small helpers ----------------------------------------------
__device__ __forceinline__ uint32_t smem_u32(const void* p) {
    return (uint32_t)__cvta_generic_to_shared(p);
}
__device__ __forceinline__ void cp_async16(uint32_t dst, const void* src) {
    asm volatile("cp.async.cg.shared.global [%0], [%1], 16;" :: "r"(dst), "l"(src));
}

// ---------------- converts: fp32 -> fp16 ---------------------------------------
namespace {
constexpr int N4_X = BL * CC / 4;     // 524288
constexpr int N4_K = HK * CC / 4;     // 131072
constexpr int N4_O = CC * CC / 4;     // 262144
}
__device__ __forceinline__ uint2 pack_h4(float4 v) {
    __half2 h0 = __floats2half2_rn(v.x, v.y);
    __half2 h1 = __floats2half2_rn(v.z, v.w);
    uint2 o;
    o.x = *(uint32_t*)&h0;
    o.y = *(uint32_t*)&h1;
    return o;
}
__global__ void __launch_bounds__(256) cvt_x_kernel(
    const float* __restrict__ x, uint2* __restrict__ xh) {
    int i = blockIdx.x * 256 + threadIdx.x;
    if (i < N4_X) xh[i] = pack_h4(((const float4*)x)[i]);
}
__global__ void __launch_bounds__(256) cvt_w_kernel(
    const float* __restrict__ kw, const float* __restrict__ ow,
    uint2* __restrict__ wkh, uint2* __restrict__ woh) {
    int i = blockIdx.x * 256 + threadIdx.x;
    if (i < N4_K)             wkh[i] = pack_h4(((const float4*)kw)[i]);
    else if (i < N4_K + N4_O) {
        int k = i - N4_K;
        woh[k] = pack_h4(((const float4*)ow)[k]);
    }
}

// ---------------- XLA/Eigen fast-tanh f32 ------------------------------------
__device__ __forceinline__ float tanh_xla(float x) {
    float xc = fminf(fmaxf(x, -7.99881172180175781f), 7.99881172180175781f);
    float x2 = __fmul_rn(xc, xc);
    float p = __fmaf_rn(x2, -2.76076847742355e-16f, 2.00018790482477e-13f);
    p = __fmaf_rn(x2, p, -8.60467152213735e-11f);
    p = __fmaf_rn(x2, p,  5.12229709037114e-08f);
    p = __fmaf_rn(x2, p,  1.48572235717979e-05f);
    p = __fmaf_rn(x2, p,  6.37261928875436e-04f);
    p = __fmaf_rn(x2, p,  4.89352455891786e-03f);
    p = __fmul_rn(xc, p);
    float q = __fmaf_rn(x2, 1.19825839466702e-06f, 1.18534705686654e-04f);
    q = __fmaf_rn(x2, q, 2.26843463243900e-03f);
    q = __fmaf_rn(x2, q, 4.89352518554385e-03f);
    float r = __fdiv_rn(p, q);
    return (fabsf(x) < 0.0004f) ? x : r;
}

// ---------------- wave: serial-FMA dots -> freq/phase (FROZEN numerics) ------
__global__ void __launch_bounds__(256) wave_exact_kernel(
    const float* __restrict__ x,
    const float* __restrict__ wave_w,   // [16, C]
    const float* __restrict__ wave_b)   // [16] (zeros)
{
    extern __shared__ float sm[];
    float* xs  = sm;                    // [16][1024]
    float* wsm = sm + 16 * CC;          // [16][WPITCH]
    __shared__ float wvs[16][16];

    const int bl0 = blockIdx.x * 16;
    const int tid = threadIdx.x;

    const uint32_t xs_base = smem_u32(xs);
    const uint32_t ws_base = smem_u32(wsm);
    #pragma unroll
    for (int i = tid; i < 16 * (CC / 4); i += 256)
        cp_async16(xs_base + i * 16, x + (size_t)bl0 * CC + i * 4);
    #pragma unroll
    for (int i = tid; i < 16 * (CC / 4); i += 256) {
        int r = i >> 8;
        int c = i & 255;
        cp_async16(ws_base + (r * WPITCH + c * 4) * 4, wave_w + i * 4);
    }
    asm volatile("cp.async.commit_group;");
    asm volatile("cp.async.wait_group 0;");
    __syncthreads();

    const int j = tid & 15;
    const int r = tid >> 4;
    const float4* wr = (const float4*)(wsm + j * WPITCH);
    const float4* xr = (const float4*)(xs + r * CC);
    float a0 = 0.0f;
    #pragma unroll 8
    for (int k4 = 0; k4 < CC / 4; k4++) {
        float4 wv = wr[k4];
        float4 xv = xr[k4];
        a0 = __fmaf_rn(xv.x, wv.x, a0);
        a0 = __fmaf_rn(xv.y, wv.y, a0);
        a0 = __fmaf_rn(xv.z, wv.z, a0);
        a0 = __fmaf_rn(xv.w, wv.w, a0);
    }
    wvs[r][j] = __fadd_rn(a0, __ldg(wave_b + j));
    __syncthreads();

    if (tid < 128) {
        int rr = tid >> 3;
        int h  = tid & 7;
        float w0 = wvs[rr][2 * h];
        float w1 = wvs[rr][2 * h + 1];
        float t0  = tanh_xla(__fmul_rn(0.5f, w0));
        float sig = __fadd_rn(0.5f, __fmul_rn(0.5f, t0));
        float freq = __fadd_rn(1.0f, __fmul_rn(sig, 15.0f));   // STRICT mul,add
        float t1 = tanh_xla(w1);
        float phase = __fmul_rn(t1, freq);
        g_freq [(bl0 + rr) * HH + h] = freq;
        g_phase[(bl0 + rr) * HH + h] = phase;
    }
}

// ---------------- fp16 tensor-core GEMM (m16n8k16, fp32 accum) ----------------
namespace { constexpr int HBK = 32, HPITCH = 40; }

template <int BM, int BN, int WM, int WN>
__global__ void __launch_bounds__(256, 1) gemm_f16_kernel(
    const __half* __restrict__ A, const __half* __restrict__ Bw,
    const float* __restrict__ bias, float* __restrict__ C,
    int M, int N, int K)
{
    constexpr int WTM = BM / WM;
    constexpr int WTN = BN / WN;
    constexpr int MF = WTM / 16;
    constexpr int NF = WTN / 8;
    static_assert(WM * WN == 8, "8 warps");

    __shared__ __half As[2][BM][HPITCH];
    __shared__ __half Bs[2][BN][HPITCH];

    const int tid = threadIdx.x;
    const int m0 = blockIdx.y * BM;
    const int n0 = blockIdx.x * BN;

    const int lane = tid & 31;
    const int g = lane >> 2;
    const int t = lane & 3;
    const int warp = tid >> 5;
    const int m_off = (warp % WM) * WTM;
    const int n_off = (warp / WM) * WTN;

    const uint32_t as_base = smem_u32(&As[0][0][0]);
    const uint32_t bs_base = smem_u32(&Bs[0][0][0]);
    const int NK = K / HBK;

    auto fill = [&](int buf, int k0) {
        #pragma unroll
        for (int i = tid; i < BM * 4; i += 256) {
            int row = i >> 2, ch = i & 3;
            cp_async16(as_base + ((buf * BM + row) * HPITCH) * 2 + ch * 16,
                       A + (size_t)(m0 + row) * K + k0 + ch * 8);
        }
        #pragma unroll
        for (int i = tid; i < BN * 4; i += 256) {
            int row = i >> 2, ch = i & 3;
            cp_async16(bs_base + ((buf * BN + row) * HPITCH) * 2 + ch * 16,
                       Bw + (size_t)(n0 + row) * K + k0 + ch * 8);
        }
    };

    float c[MF][NF][4];
    #pragma unroll
    for (int i = 0; i < MF; i++)
        #pragma unroll
        for (int jj = 0; jj < NF; jj++)
            #pragma unroll
            for (int q = 0; q < 4; q++) c[i][jj][q] = 0.0f;

    fill(0, 0);
    asm volatile("cp.async.commit_group;");

    for (int it = 0; it < NK; ++it) {
        if (it + 1 < NK) {
            fill((it + 1) & 1, (it + 1) * HBK);
            asm volatile("cp.async.commit_group;");
            asm volatile("cp.async.wait_group 1;");
        } else {
            asm volatile("cp.async.wait_group 0;");
        }
        __syncthreads();

        const int buf = it & 1;
        #pragma unroll
        for (int ks = 0; ks < 2; ks++) {
            const int k16 = ks * 16;
            uint32_t a[MF][4], b[NF][2];
            #pragma unroll
            for (int mf = 0; mf < MF; mf++) {
                const __half* r0 = &As[buf][m_off + 16 * mf + g    ][k16 + 2 * t];
                const __half* r1 = &As[buf][m_off + 16 * mf + g + 8][k16 + 2 * t];
                a[mf][0] = *(const uint32_t*)(r0);
                a[mf][1] = *(const uint32_t*)(r1);
                a[mf][2] = *(const uint32_t*)(r0 + 8);
                a[mf][3] = *(const uint32_t*)(r1 + 8);
            }
            #pragma unroll
            for (int nf = 0; nf < NF; nf++) {
                const __half* br = &Bs[buf][n_off + 8 * nf + g][k16 + 2 * t];
                b[nf][0] = *(const uint32_t*)(br);
                b[nf][1] = *(const uint32_t*)(br + 8);
            }
            #pragma unroll
            for (int mf = 0; mf < MF; mf++)
                #pragma unroll
                for (int nf = 0; nf < NF; nf++)
                    asm volatile(
                        "mma.sync.aligned.m16n8k16.row.col.f32.f16.f16.f32 "
                        "{%0,%1,%2,%3}, {%4,%5,%6,%7}, {%8,%9}, {%0,%1,%2,%3};"
                        : "+f"(c[mf][nf][0]), "+f"(c[mf][nf][1]),
                          "+f"(c[mf][nf][2]), "+f"(c[mf][nf][3])
                        : "r"(a[mf][0]), "r"(a[mf][1]), "r"(a[mf][2]), "r"(a[mf][3]),
                          "r"(b[nf][0]), "r"(b[nf][1]));
        }
        __syncthreads();
    }

    #pragma unroll
    for (int nf = 0; nf < NF; nf++) {
        int col = n0 + n_off + 8 * nf + 2 * t;
        float bb0 = 0.0f, bb1 = 0.0f;
        if (bias) { bb0 = __ldg(bias + col); bb1 = __ldg(bias + col + 1); }
        #pragma unroll
        for (int mf = 0; mf < MF; mf++) {
            int row = m0 + m_off + 16 * mf + g;
            float2 v0 = make_float2(c[mf][nf][0] + bb0, c[mf][nf][1] + bb1);
            *(float2*)(C + (size_t)row * N + col) = v0;
            float2 v1 = make_float2(c[mf][nf][2] + bb0, c[mf][nf][3] + bb1);
            *(float2*)(C + (size_t)(row + 8) * N + col) = v1;
        }
    }
}

// ---------------- gather: uint4 (8ch) loads, 2 positions/block ---------------
__global__ void __launch_bounds__(256) gather_kernel(const __half* __restrict__ xh)
{
    __shared__ float   ws  [2][HH][SS];
    __shared__ __half2 fr2s[2][HH][SS];
    __shared__ int     i0s [2][HH][SS];   // row offsets in uint4 units (i*CC/8)
    __shared__ int     i1s [2][HH][SS];

    const int bl0 = blockIdx.x * 2;
    const int tid = threadIdx.x;

    #pragma unroll
    for (int idx = tid; idx < 2 * HH * SS; idx += 256) {
        // per (p,h,s) tap parameters — FROZEN strict unfused fp32
        int p = idx >> 8;
        int h = (idx >> 5) & 7;
        int s = idx & 31;
        int bl = bl0 + p;
        int l  = bl & (LL - 1);
        float freq  = g_freq [bl * HH + h];
        float phase = g_phase[bl * HH + h];
        float tap   = (float)(s - 16) + 0.5f;
        float offs  = __fadd_rn(phase, __fmul_rn(freq, tap));   // NO fma
        float pos   = __fadd_rn((float)l, offs);
        pos = fmaxf(pos, 0.0f);
        pos = fminf(pos, (float)(LL - 1));
        float i0f  = floorf(pos);
        float frac = __fsub_rn(pos, i0f);
        int i0 = (int)i0f;
        int i1 = min(i0 + 1, LL - 1);
        float tb = __fmul_rn(__fadd_rn(offs, 256.0f), 0.125f);
        int bin = (int)floorf(tb);
        bin = max(0, min(bin, KK - 1));
        ws  [p][h][s] = g_kmat[((size_t)bl * HH + h) * KK + bin];
        fr2s[p][h][s] = __float2half2_rn(frac);
        i0s [p][h][s] = i0 * (CC / 8);
        i1s [p][h][s] = i1 * (CC / 8);
    }
    __syncthreads();

    // 256 threads: warps 0-3 -> position 0, warps 4-7 -> position 1.
    // 128 threads x 8 channels = 1024 channels per position.
    const int p    = tid >> 7;
    const int bl   = bl0 + p;
    const int b    = bl >> 10;
    const int t128 = tid & 127;
    const int h    = t128 >> 4;        // 16 uint4 per head (128 ch)
    const int d8   = t128 & 15;
    const uint4* base = (const uint4*)(xh + (size_t)b * (LL * CC)) + h * (DD / 8) + d8;

    float acc[8];
    #pragma unroll
    for (int q = 0; q < 8; q++) acc[q] = 0.0f;

    #pragma unroll 8
    for (int s = 0; s < SS; s++) {
        uint4 u0 = __ldg(base + i0s[p][h][s]);
        uint4 u1 = __ldg(base + i1s[p][h][s]);
        __half2 fr = fr2s[p][h][s];
        float w = ws[p][h][s];
        const uint32_t* p0 = &u0.x;
        const uint32_t* p1 = &u1.x;
        #pragma unroll
        for (int q = 0; q < 4; q++) {
            __half2 f0 = *(__half2*)&p0[q];
            __half2 f1 = *(__half2*)&p1[q];
            __half2 gh = __hfma2(fr, __hsub2(f1, f0), f0);
            float2 gf = __half22float2(gh);
            acc[2 * q    ] = __fmaf_rn(w, gf.x, acc[2 * q    ]);
            acc[2 * q + 1] = __fmaf_rn(w, gf.y, acc[2 * q + 1]);
        }
    }

    uint4 o;
    uint32_t* po = &o.x;
    #pragma unroll
    for (int q = 0; q < 4; q++) {
        __half2 oh = __floats2half2_rn(acc[2 * q], acc[2 * q + 1]);
        po[q] = *(uint32_t*)&oh;
    }
    ((uint4*)g_yh)[(size_t)bl * (CC / 8) + t128] = o;
}

// ---------------- launch -----------------------------------------------------
extern "C" void kernel_launch(void* const* d_in, const int* in_sizes, int n_in,
                              void* d_out, int out_size) {
    const float* x        = (const float*)d_in[0];
    const float* wave_w   = (const float*)d_in[1];
    const float* wave_b   = (const float*)d_in[2];
    const float* kernel_w = (const float*)d_in[3];
    const float* kernel_b = (const float*)d_in[4];
    const float* out_w    = (const float*)d_in[5];
    float* out = (float*)d_out;

    float *p_kmat;
    __half *p_xh, *p_yh, *p_wkh, *p_woh;
    cudaGetSymbolAddress((void**)&p_kmat, g_kmat);
    cudaGetSymbolAddress((void**)&p_xh,   g_xh);
    cudaGetSymbolAddress((void**)&p_yh,   g_yh);
    cudaGetSymbolAddress((void**)&p_wkh,  g_wkh);
    cudaGetSymbolAddress((void**)&p_woh,  g_woh);

    // side stream: weight converts (ev_w) then wave (ev_wave).
    // Handles created per-call, intentionally not destroyed (capture-legal).
    cudaStream_t s2;
    cudaEvent_t ev_fork, ev_w, ev_wave;
    cudaStreamCreateWithFlags(&s2, cudaStreamNonBlocking);
    cudaEventCreateWithFlags(&ev_fork, cudaEventDisableTiming);
    cudaEventCreateWithFlags(&ev_w,    cudaEventDisableTiming);
    cudaEventCreateWithFlags(&ev_wave, cudaEventDisableTiming);

    constexpr int WAVE_SMEM = (16 * CC + 16 * WPITCH) * 4;   // ~130 KB
    cudaFuncSetAttribute(wave_exact_kernel,
                         cudaFuncAttributeMaxDynamicSharedMemorySize, WAVE_SMEM);

    cudaEventRecord(ev_fork, 0);
    cudaStreamWaitEvent(s2, ev_fork, 0);
    cvt_w_kernel<<<(N4_K + N4_O + 255) / 256, 256, 0, s2>>>(
        kernel_w, out_w, (uint2*)p_wkh, (uint2*)p_woh);
    cudaEventRecord(ev_w, s2);
    wave_exact_kernel<<<BL / 16, 256, WAVE_SMEM, s2>>>(x, wave_w, wave_b);
    cudaEventRecord(ev_wave, s2);

    // main stream
    cvt_x_kernel<<<(N4_X + 255) / 256, 256>>>(x, (uint2*)p_xh);
    cudaStreamWaitEvent(0, ev_w, 0);
    gemm_f16_kernel<64, 128, 2, 4><<<dim3(HK / 128, BL / 64), 256>>>(
        p_xh, p_wkh, kernel_b, p_kmat, BL, HK, CC);
    cudaStreamWaitEvent(0, ev_wave, 0);
    gather_kernel<<<BL / 2, 256>>>(p_xh);
    gemm_f16_kernel<128, 128, 4, 2><<<dim3(CC / 128, BL / 128), 256>>>(
        p_yh, p_woh, nullptr, out, BL, CC, CC);

    (void)in_sizes; (void)n_in; (void)out_size;
}

// round 11
// speedup vs baseline: 1.1396x; 1.1396x over previous
#include <cuda_runtime.h>
#include <cuda_fp16.h>
#include <math.h>
#include <stdint.h>

// Problem constants (fixed by setup_inputs)
namespace {
constexpr int BB = 2;
constexpr int LL = 1024;
constexpr int CC = 1024;
constexpr int HH = 8;
constexpr int DD = 128;   // CC / HH
constexpr int SS = 32;    // sample taps
constexpr int KK = 64;    // kernel taps
constexpr int BL = BB * LL;           // 2048
constexpr int HK = HH * KK;           // 512
constexpr int WPITCH = 1028;          // wave_w smem pitch (floats)
}

// ---------------- scratch (static device globals; no runtime allocation) ----
__device__ float  g_freq [BL * HH];
__device__ float  g_phase[BL * HH];
__device__ float  g_kmat [BL * HK];       // 4 MB (fp32 accum out of f16 GEMM)
__device__ __half g_yh   [BL * CC];       // 4 MB y (fp16)
__device__ __half g_xh   [BL * CC];       // 4 MB x (fp16): gather + kmat A
__device__ __half g_wkh  [HK * CC];       // kernel_w fp16 [N][K]
__device__ __half g_woh  [CC * CC];       // out_w fp16 [N][K]

// ---------------- small helpers ----------------------------------------------
__device__ __forceinline__ uint32_t smem_u32(const void* p) {
    return (uint32_t)__cvta_generic_to_shared(p);
}
__device__ __forceinline__ void cp_async16(uint32_t dst, const void* src) {
    asm volatile("cp.async.cg.shared.global [%0], [%1], 16;" :: "r"(dst), "l"(src));
}

// ---------------- fused converts: fp32 -> fp16 --------------------------------
namespace {
constexpr int N4_X = BL * CC / 4;     // 524288
constexpr int N4_K = HK * CC / 4;     // 131072
constexpr int N4_O = CC * CC / 4;     // 262144
constexpr int N4_TOT = N4_X + N4_K + N4_O;
}
__device__ __forceinline__ uint2 pack_h4(float4 v) {
    __half2 h0 = __floats2half2_rn(v.x, v.y);
    __half2 h1 = __floats2half2_rn(v.z, v.w);
    uint2 o;
    o.x = *(uint32_t*)&h0;
    o.y = *(uint32_t*)&h1;
    return o;
}
__global__ void __launch_bounds__(256) cvt_all_kernel(
    const float* __restrict__ x, const float* __restrict__ kw,
    const float* __restrict__ ow,
    uint2* __restrict__ xh, uint2* __restrict__ wkh, uint2* __restrict__ woh) {
    int i = blockIdx.x * 256 + threadIdx.x;
    if (i < N4_X)             xh[i] = pack_h4(((const float4*)x)[i]);
    else if (i < N4_X + N4_K) {
        int k = i - N4_X;
        wkh[k] = pack_h4(((const float4*)kw)[k]);
    } else if (i < N4_TOT) {
        int k = i - N4_X - N4_K;
        woh[k] = pack_h4(((const float4*)ow)[k]);
    }
}

// ---------------- XLA/Eigen fast-tanh f32 ------------------------------------
__device__ __forceinline__ float tanh_xla(float x) {
    float xc = fminf(fmaxf(x, -7.99881172180175781f), 7.99881172180175781f);
    float x2 = __fmul_rn(xc, xc);
    float p = __fmaf_rn(x2, -2.76076847742355e-16f, 2.00018790482477e-13f);
    p = __fmaf_rn(x2, p, -8.60467152213735e-11f);
    p = __fmaf_rn(x2, p,  5.12229709037114e-08f);
    p = __fmaf_rn(x2, p,  1.48572235717979e-05f);
    p = __fmaf_rn(x2, p,  6.37261928875436e-04f);
    p = __fmaf_rn(x2, p,  4.89352455891786e-03f);
    p = __fmul_rn(xc, p);
    float q = __fmaf_rn(x2, 1.19825839466702e-06f, 1.18534705686654e-04f);
    q = __fmaf_rn(x2, q, 2.26843463243900e-03f);
    q = __fmaf_rn(x2, q, 4.89352518554385e-03f);
    float r = __fdiv_rn(p, q);
    return (fabsf(x) < 0.0004f) ? x : r;
}

// ---------------- wave: serial-FMA dots -> freq/phase (FROZEN numerics) ------
__global__ void __launch_bounds__(256) wave_exact_kernel(
    const float* __restrict__ x,
    const float* __restrict__ wave_w,   // [16, C]
    const float* __restrict__ wave_b)   // [16] (zeros)
{
    extern __shared__ float sm[];
    float* xs  = sm;                    // [16][1024]
    float* wsm = sm + 16 * CC;          // [16][WPITCH]
    __shared__ float wvs[16][16];

    const int bl0 = blockIdx.x * 16;
    const int tid = threadIdx.x;

    const uint32_t xs_base = smem_u32(xs);
    const uint32_t ws_base = smem_u32(wsm);
    #pragma unroll
    for (int i = tid; i < 16 * (CC / 4); i += 256)
        cp_async16(xs_base + i * 16, x + (size_t)bl0 * CC + i * 4);
    #pragma unroll
    for (int i = tid; i < 16 * (CC / 4); i += 256) {
        int r = i >> 8;
        int c = i & 255;
        cp_async16(ws_base + (r * WPITCH + c * 4) * 4, wave_w + i * 4);
    }
    asm volatile("cp.async.commit_group;");
    asm volatile("cp.async.wait_group 0;");
    __syncthreads();

    const int j = tid & 15;
    const int r = tid >> 4;
    const float4* wr = (const float4*)(wsm + j * WPITCH);
    const float4* xr = (const float4*)(xs + r * CC);
    float a0 = 0.0f;
    #pragma unroll 8
    for (int k4 = 0; k4 < CC / 4; k4++) {
        float4 wv = wr[k4];
        float4 xv = xr[k4];
        a0 = __fmaf_rn(xv.x, wv.x, a0);
        a0 = __fmaf_rn(xv.y, wv.y, a0);
        a0 = __fmaf_rn(xv.z, wv.z, a0);
        a0 = __fmaf_rn(xv.w, wv.w, a0);
    }
    wvs[r][j] = __fadd_rn(a0, __ldg(wave_b + j));
    __syncthreads();

    if (tid < 128) {
        int rr = tid >> 3;
        int h  = tid & 7;
        float w0 = wvs[rr][2 * h];
        float w1 = wvs[rr][2 * h + 1];
        float t0  = tanh_xla(__fmul_rn(0.5f, w0));
        float sig = __fadd_rn(0.5f, __fmul_rn(0.5f, t0));
        float freq = __fadd_rn(1.0f, __fmul_rn(sig, 15.0f));   // STRICT mul,add
        float t1 = tanh_xla(w1);
        float phase = __fmul_rn(t1, freq);
        g_freq [(bl0 + rr) * HH + h] = freq;
        g_phase[(bl0 + rr) * HH + h] = phase;
    }
}

// ---------------- fp16 tensor-core GEMM (m16n8k16, fp32 accum) ----------------
namespace { constexpr int HBK = 32, HPITCH = 40; }

template <int BM, int BN, int WM, int WN>
__global__ void __launch_bounds__(256, 1) gemm_f16_kernel(
    const __half* __restrict__ A, const __half* __restrict__ Bw,
    const float* __restrict__ bias, float* __restrict__ C,
    int M, int N, int K)
{
    constexpr int WTM = BM / WM;
    constexpr int WTN = BN / WN;
    constexpr int MF = WTM / 16;
    constexpr int NF = WTN / 8;
    static_assert(WM * WN == 8, "8 warps");

    __shared__ __half As[2][BM][HPITCH];
    __shared__ __half Bs[2][BN][HPITCH];

    const int tid = threadIdx.x;
    const int m0 = blockIdx.y * BM;
    const int n0 = blockIdx.x * BN;

    const int lane = tid & 31;
    const int g = lane >> 2;
    const int t = lane & 3;
    const int warp = tid >> 5;
    const int m_off = (warp % WM) * WTM;
    const int n_off = (warp / WM) * WTN;

    const uint32_t as_base = smem_u32(&As[0][0][0]);
    const uint32_t bs_base = smem_u32(&Bs[0][0][0]);
    const int NK = K / HBK;

    auto fill = [&](int buf, int k0) {
        #pragma unroll
        for (int i = tid; i < BM * 4; i += 256) {
            int row = i >> 2, ch = i & 3;
            cp_async16(as_base + ((buf * BM + row) * HPITCH) * 2 + ch * 16,
                       A + (size_t)(m0 + row) * K + k0 + ch * 8);
        }
        #pragma unroll
        for (int i = tid; i < BN * 4; i += 256) {
            int row = i >> 2, ch = i & 3;
            cp_async16(bs_base + ((buf * BN + row) * HPITCH) * 2 + ch * 16,
                       Bw + (size_t)(n0 + row) * K + k0 + ch * 8);
        }
    };

    float c[MF][NF][4];
    #pragma unroll
    for (int i = 0; i < MF; i++)
        #pragma unroll
        for (int jj = 0; jj < NF; jj++)
            #pragma unroll
            for (int q = 0; q < 4; q++) c[i][jj][q] = 0.0f;

    fill(0, 0);
    asm volatile("cp.async.commit_group;");

    for (int it = 0; it < NK; ++it) {
        if (it + 1 < NK) {
            fill((it + 1) & 1, (it + 1) * HBK);
            asm volatile("cp.async.commit_group;");
            asm volatile("cp.async.wait_group 1;");
        } else {
            asm volatile("cp.async.wait_group 0;");
        }
        __syncthreads();

        const int buf = it & 1;
        #pragma unroll
        for (int ks = 0; ks < 2; ks++) {
            const int k16 = ks * 16;
            uint32_t a[MF][4], b[NF][2];
            #pragma unroll
            for (int mf = 0; mf < MF; mf++) {
                const __half* r0 = &As[buf][m_off + 16 * mf + g    ][k16 + 2 * t];
                const __half* r1 = &As[buf][m_off + 16 * mf + g + 8][k16 + 2 * t];
                a[mf][0] = *(const uint32_t*)(r0);
                a[mf][1] = *(const uint32_t*)(r1);
                a[mf][2] = *(const uint32_t*)(r0 + 8);
                a[mf][3] = *(const uint32_t*)(r1 + 8);
            }
            #pragma unroll
            for (int nf = 0; nf < NF; nf++) {
                const __half* br = &Bs[buf][n_off + 8 * nf + g][k16 + 2 * t];
                b[nf][0] = *(const uint32_t*)(br);
                b[nf][1] = *(const uint32_t*)(br + 8);
            }
            #pragma unroll
            for (int mf = 0; mf < MF; mf++)
                #pragma unroll
                for (int nf = 0; nf < NF; nf++)
                    asm volatile(
                        "mma.sync.aligned.m16n8k16.row.col.f32.f16.f16.f32 "
                        "{%0,%1,%2,%3}, {%4,%5,%6,%7}, {%8,%9}, {%0,%1,%2,%3};"
                        : "+f"(c[mf][nf][0]), "+f"(c[mf][nf][1]),
                          "+f"(c[mf][nf][2]), "+f"(c[mf][nf][3])
                        : "r"(a[mf][0]), "r"(a[mf][1]), "r"(a[mf][2]), "r"(a[mf][3]),
                          "r"(b[nf][0]), "r"(b[nf][1]));
        }
        __syncthreads();
    }

    #pragma unroll
    for (int nf = 0; nf < NF; nf++) {
        int col = n0 + n_off + 8 * nf + 2 * t;
        float bb0 = 0.0f, bb1 = 0.0f;
        if (bias) { bb0 = __ldg(bias + col); bb1 = __ldg(bias + col + 1); }
        #pragma unroll
        for (int mf = 0; mf < MF; mf++) {
            int row = m0 + m_off + 16 * mf + g;
            float2 v0 = make_float2(c[mf][nf][0] + bb0, c[mf][nf][1] + bb1);
            *(float2*)(C + (size_t)row * N + col) = v0;
            float2 v1 = make_float2(c[mf][nf][2] + bb0, c[mf][nf][3] + bb1);
            *(float2*)(C + (size_t)(row + 8) * N + col) = v1;
        }
    }
}

// ---------------- gather: uint4 (8ch) loads, 2 positions/block ---------------
__global__ void __launch_bounds__(256) gather_kernel(const __half* __restrict__ xh)
{
    __shared__ float   ws  [2][HH][SS];
    __shared__ __half2 fr2s[2][HH][SS];
    __shared__ int     i0s [2][HH][SS];   // row offsets in uint4 units (i*CC/8)
    __shared__ int     i1s [2][HH][SS];

    const int bl0 = blockIdx.x * 2;
    const int tid = threadIdx.x;

    #pragma unroll
    for (int idx = tid; idx < 2 * HH * SS; idx += 256) {
        // per (p,h,s) tap parameters — FROZEN strict unfused fp32
        int p = idx >> 8;
        int h = (idx >> 5) & 7;
        int s = idx & 31;
        int bl = bl0 + p;
        int l  = bl & (LL - 1);
        float freq  = g_freq [bl * HH + h];
        float phase = g_phase[bl * HH + h];
        float tap   = (float)(s - 16) + 0.5f;
        float offs  = __fadd_rn(phase, __fmul_rn(freq, tap));   // NO fma
        float pos   = __fadd_rn((float)l, offs);
        pos = fmaxf(pos, 0.0f);
        pos = fminf(pos, (float)(LL - 1));
        float i0f  = floorf(pos);
        float frac = __fsub_rn(pos, i0f);
        int i0 = (int)i0f;
        int i1 = min(i0 + 1, LL - 1);
        float tb = __fmul_rn(__fadd_rn(offs, 256.0f), 0.125f);
        int bin = (int)floorf(tb);
        bin = max(0, min(bin, KK - 1));
        ws  [p][h][s] = g_kmat[((size_t)bl * HH + h) * KK + bin];
        fr2s[p][h][s] = __float2half2_rn(frac);
        i0s [p][h][s] = i0 * (CC / 8);
        i1s [p][h][s] = i1 * (CC / 8);
    }
    __syncthreads();

    // 256 threads: warps 0-3 -> position 0, warps 4-7 -> position 1.
    const int p    = tid >> 7;
    const int bl   = bl0 + p;
    const int b    = bl >> 10;
    const int t128 = tid & 127;
    const int h    = t128 >> 4;        // 16 uint4 per head (128 ch)
    const int d8   = t128 & 15;
    const uint4* base = (const uint4*)(xh + (size_t)b * (LL * CC)) + h * (DD / 8) + d8;

    float acc[8];
    #pragma unroll
    for (int q = 0; q < 8; q++) acc[q] = 0.0f;

    #pragma unroll 8
    for (int s = 0; s < SS; s++) {
        uint4 u0 = __ldg(base + i0s[p][h][s]);
        uint4 u1 = __ldg(base + i1s[p][h][s]);
        __half2 fr = fr2s[p][h][s];
        float w = ws[p][h][s];
        const uint32_t* p0 = &u0.x;
        const uint32_t* p1 = &u1.x;
        #pragma unroll
        for (int q = 0; q < 4; q++) {
            __half2 f0 = *(__half2*)&p0[q];
            __half2 f1 = *(__half2*)&p1[q];
            __half2 gh = __hfma2(fr, __hsub2(f1, f0), f0);
            float2 gf = __half22float2(gh);
            acc[2 * q    ] = __fmaf_rn(w, gf.x, acc[2 * q    ]);
            acc[2 * q + 1] = __fmaf_rn(w, gf.y, acc[2 * q + 1]);
        }
    }

    uint4 o;
    uint32_t* po = &o.x;
    #pragma unroll
    for (int q = 0; q < 4; q++) {
        __half2 oh = __floats2half2_rn(acc[2 * q], acc[2 * q + 1]);
        po[q] = *(uint32_t*)&oh;
    }
    ((uint4*)g_yh)[(size_t)bl * (CC / 8) + t128] = o;
}

// ---------------- launch -----------------------------------------------------
extern "C" void kernel_launch(void* const* d_in, const int* in_sizes, int n_in,
                              void* d_out, int out_size) {
    const float* x        = (const float*)d_in[0];
    const float* wave_w   = (const float*)d_in[1];
    const float* wave_b   = (const float*)d_in[2];
    const float* kernel_w = (const float*)d_in[3];
    const float* kernel_b = (const float*)d_in[4];
    const float* out_w    = (const float*)d_in[5];
    float* out = (float*)d_out;

    float *p_kmat;
    __half *p_xh, *p_yh, *p_wkh, *p_woh;
    cudaGetSymbolAddress((void**)&p_kmat, g_kmat);
    cudaGetSymbolAddress((void**)&p_xh,   g_xh);
    cudaGetSymbolAddress((void**)&p_yh,   g_yh);
    cudaGetSymbolAddress((void**)&p_wkh,  g_wkh);
    cudaGetSymbolAddress((void**)&p_woh,  g_woh);

    // side stream: wave only (depends on raw x). It overlaps ONLY the convert
    // kernel (zero-smem blocks co-reside with wave's 130KB-smem blocks); the
    // join happens BEFORE kmat so the GEMMs run on an uncontended machine.
    cudaStream_t s2;
    cudaEvent_t ev_fork, ev_wave;
    cudaStreamCreateWithFlags(&s2, cudaStreamNonBlocking);
    cudaEventCreateWithFlags(&ev_fork, cudaEventDisableTiming);
    cudaEventCreateWithFlags(&ev_wave, cudaEventDisableTiming);

    constexpr int WAVE_SMEM = (16 * CC + 16 * WPITCH) * 4;   // ~130 KB
    cudaFuncSetAttribute(wave_exact_kernel,
                         cudaFuncAttributeMaxDynamicSharedMemorySize, WAVE_SMEM);

    cudaEventRecord(ev_fork, 0);
    cudaStreamWaitEvent(s2, ev_fork, 0);
    wave_exact_kernel<<<BL / 16, 256, WAVE_SMEM, s2>>>(x, wave_w, wave_b);
    cudaEventRecord(ev_wave, s2);

    // main stream: fused converts (overlap wave), then join, then GEMM chain
    cvt_all_kernel<<<(N4_TOT + 255) / 256, 256>>>(
        x, kernel_w, out_w, (uint2*)p_xh, (uint2*)p_wkh, (uint2*)p_woh);
    cudaStreamWaitEvent(0, ev_wave, 0);
    gemm_f16_kernel<64, 128, 2, 4><<<dim3(HK / 128, BL / 64), 256>>>(
        p_xh, p_wkh, kernel_b, p_kmat, BL, HK, CC);
    gather_kernel<<<BL / 2, 256>>>(p_xh);
    gemm_f16_kernel<128, 128, 4, 2><<<dim3(CC / 128, BL / 128), 256>>>(
        p_yh, p_woh, nullptr, out, BL, CC, CC);

    (void)in_sizes; (void)n_in; (void)out_size;
}

// round 12
// speedup vs baseline: 1.1406x; 1.0009x over previous
#include <cuda_runtime.h>
#include <cuda_fp16.h>
#include <math.h>
#include <stdint.h>

// Problem constants (fixed by setup_inputs)
namespace {
constexpr int BB = 2;
constexpr int LL = 1024;
constexpr int CC = 1024;
constexpr int HH = 8;
constexpr int DD = 128;   // CC / HH
constexpr int SS = 32;    // sample taps
constexpr int KK = 64;    // kernel taps
constexpr int BL = BB * LL;           // 2048
constexpr int HK = HH * KK;           // 512
constexpr int WPITCH = 1028;          // wave_w smem pitch (floats)
}

// ---------------- scratch (static device globals; no runtime allocation) ----
__device__ float  g_freq [BL * HH];
__device__ float  g_phase[BL * HH];
__device__ float  g_kmat [BL * HK];       // 4 MB (fp32 accum out of f16 GEMM)
__device__ __half g_yh   [BL * CC];       // 4 MB y (fp16)
__device__ __half g_xh   [BL * CC];       // 4 MB x (fp16): gather + kmat A
__device__ __half g_wkh  [HK * CC];       // kernel_w fp16 [N][K]
__device__ __half g_woh  [CC * CC];       // out_w fp16 [N][K]

// ---------------- small helpers ----------------------------------------------
__device__ __forceinline__ uint32_t smem_u32(const void* p) {
    return (uint32_t)__cvta_generic_to_shared(p);
}
__device__ __forceinline__ void cp_async16(uint32_t dst, const void* src) {
    asm volatile("cp.async.cg.shared.global [%0], [%1], 16;" :: "r"(dst), "l"(src));
}
__device__ __forceinline__ void ldsm_x4(uint32_t (&r)[4], uint32_t addr) {
    asm volatile("ldmatrix.sync.aligned.m8n8.x4.shared.b16 {%0,%1,%2,%3}, [%4];"
        : "=r"(r[0]), "=r"(r[1]), "=r"(r[2]), "=r"(r[3]) : "r"(addr));
}
__device__ __forceinline__ void ldsm_x2(uint32_t& r0, uint32_t& r1, uint32_t addr) {
    asm volatile("ldmatrix.sync.aligned.m8n8.x2.shared.b16 {%0,%1}, [%2];"
        : "=r"(r0), "=r"(r1) : "r"(addr));
}

// ---------------- fused converts: fp32 -> fp16 --------------------------------
namespace {
constexpr int N4_X = BL * CC / 4;     // 524288
constexpr int N4_K = HK * CC / 4;     // 131072
constexpr int N4_O = CC * CC / 4;     // 262144
constexpr int N4_TOT = N4_X + N4_K + N4_O;
}
__device__ __forceinline__ uint2 pack_h4(float4 v) {
    __half2 h0 = __floats2half2_rn(v.x, v.y);
    __half2 h1 = __floats2half2_rn(v.z, v.w);
    uint2 o;
    o.x = *(uint32_t*)&h0;
    o.y = *(uint32_t*)&h1;
    return o;
}
__global__ void __launch_bounds__(256) cvt_all_kernel(
    const float* __restrict__ x, const float* __restrict__ kw,
    const float* __restrict__ ow,
    uint2* __restrict__ xh, uint2* __restrict__ wkh, uint2* __restrict__ woh) {
    int i = blockIdx.x * 256 + threadIdx.x;
    if (i < N4_X)             xh[i] = pack_h4(((const float4*)x)[i]);
    else if (i < N4_X + N4_K) {
        int k = i - N4_X;
        wkh[k] = pack_h4(((const float4*)kw)[k]);
    } else if (i < N4_TOT) {
        int k = i - N4_X - N4_K;
        woh[k] = pack_h4(((const float4*)ow)[k]);
    }
}

// ---------------- XLA/Eigen fast-tanh f32 ------------------------------------
__device__ __forceinline__ float tanh_xla(float x) {
    float xc = fminf(fmaxf(x, -7.99881172180175781f), 7.99881172180175781f);
    float x2 = __fmul_rn(xc, xc);
    float p = __fmaf_rn(x2, -2.76076847742355e-16f, 2.00018790482477e-13f);
    p = __fmaf_rn(x2, p, -8.60467152213735e-11f);
    p = __fmaf_rn(x2, p,  5.12229709037114e-08f);
    p = __fmaf_rn(x2, p,  1.48572235717979e-05f);
    p = __fmaf_rn(x2, p,  6.37261928875436e-04f);
    p = __fmaf_rn(x2, p,  4.89352455891786e-03f);
    p = __fmul_rn(xc, p);
    float q = __fmaf_rn(x2, 1.19825839466702e-06f, 1.18534705686654e-04f);
    q = __fmaf_rn(x2, q, 2.26843463243900e-03f);
    q = __fmaf_rn(x2, q, 4.89352518554385e-03f);
    float r = __fdiv_rn(p, q);
    return (fabsf(x) < 0.0004f) ? x : r;
}

// ---------------- wave: serial-FMA dots -> freq/phase (FROZEN numerics) ------
__global__ void __launch_bounds__(256) wave_exact_kernel(
    const float* __restrict__ x,
    const float* __restrict__ wave_w,   // [16, C]
    const float* __restrict__ wave_b)   // [16] (zeros)
{
    extern __shared__ float sm[];
    float* xs  = sm;                    // [16][1024]
    float* wsm = sm + 16 * CC;          // [16][WPITCH]
    __shared__ float wvs[16][16];

    const int bl0 = blockIdx.x * 16;
    const int tid = threadIdx.x;

    const uint32_t xs_base = smem_u32(xs);
    const uint32_t ws_base = smem_u32(wsm);
    #pragma unroll
    for (int i = tid; i < 16 * (CC / 4); i += 256)
        cp_async16(xs_base + i * 16, x + (size_t)bl0 * CC + i * 4);
    #pragma unroll
    for (int i = tid; i < 16 * (CC / 4); i += 256) {
        int r = i >> 8;
        int c = i & 255;
        cp_async16(ws_base + (r * WPITCH + c * 4) * 4, wave_w + i * 4);
    }
    asm volatile("cp.async.commit_group;");
    asm volatile("cp.async.wait_group 0;");
    __syncthreads();

    const int j = tid & 15;
    const int r = tid >> 4;
    const float4* wr = (const float4*)(wsm + j * WPITCH);
    const float4* xr = (const float4*)(xs + r * CC);
    float a0 = 0.0f;
    #pragma unroll 8
    for (int k4 = 0; k4 < CC / 4; k4++) {
        float4 wv = wr[k4];
        float4 xv = xr[k4];
        a0 = __fmaf_rn(xv.x, wv.x, a0);
        a0 = __fmaf_rn(xv.y, wv.y, a0);
        a0 = __fmaf_rn(xv.z, wv.z, a0);
        a0 = __fmaf_rn(xv.w, wv.w, a0);
    }
    wvs[r][j] = __fadd_rn(a0, __ldg(wave_b + j));
    __syncthreads();

    if (tid < 128) {
        int rr = tid >> 3;
        int h  = tid & 7;
        float w0 = wvs[rr][2 * h];
        float w1 = wvs[rr][2 * h + 1];
        float t0  = tanh_xla(__fmul_rn(0.5f, w0));
        float sig = __fadd_rn(0.5f, __fmul_rn(0.5f, t0));
        float freq = __fadd_rn(1.0f, __fmul_rn(sig, 15.0f));   // STRICT mul,add
        float t1 = tanh_xla(w1);
        float phase = __fmul_rn(t1, freq);
        g_freq [(bl0 + rr) * HH + h] = freq;
        g_phase[(bl0 + rr) * HH + h] = phase;
    }
}

// ---------------- fp16 tensor-core GEMM (m16n8k16, fp32 accum, ldmatrix) ------
namespace { constexpr int HBK = 32, HPITCH = 40; }

template <int BM, int BN, int WM, int WN>
__global__ void __launch_bounds__(256, 1) gemm_f16_kernel(
    const __half* __restrict__ A, const __half* __restrict__ Bw,
    const float* __restrict__ bias, float* __restrict__ C,
    int M, int N, int K)
{
    constexpr int WTM = BM / WM;
    constexpr int WTN = BN / WN;
    constexpr int MF = WTM / 16;
    constexpr int NF = WTN / 8;
    static_assert(WM * WN == 8, "8 warps");

    __shared__ __half As[2][BM][HPITCH];
    __shared__ __half Bs[2][BN][HPITCH];

    const int tid = threadIdx.x;
    const int m0 = blockIdx.y * BM;
    const int n0 = blockIdx.x * BN;

    const int lane = tid & 31;
    const int g = lane >> 2;
    const int t = lane & 3;
    const int warp = tid >> 5;
    const int m_off = (warp % WM) * WTM;
    const int n_off = (warp / WM) * WTN;

    // ldmatrix per-lane address components
    const int a_row_lane = ((lane >> 3) & 1) * 8 + (lane & 7);  // row-group + row
    const int a_k_lane   = (lane >> 4) * 8;                     // k-half
    const int b_row_lane = lane & 7;
    const int b_k_lane   = ((lane >> 3) & 1) * 8;

    const uint32_t as_base = smem_u32(&As[0][0][0]);
    const uint32_t bs_base = smem_u32(&Bs[0][0][0]);
    const int NK = K / HBK;

    auto fill = [&](int buf, int k0) {
        #pragma unroll
        for (int i = tid; i < BM * 4; i += 256) {
            int row = i >> 2, ch = i & 3;
            cp_async16(as_base + ((buf * BM + row) * HPITCH) * 2 + ch * 16,
                       A + (size_t)(m0 + row) * K + k0 + ch * 8);
        }
        #pragma unroll
        for (int i = tid; i < BN * 4; i += 256) {
            int row = i >> 2, ch = i & 3;
            cp_async16(bs_base + ((buf * BN + row) * HPITCH) * 2 + ch * 16,
                       Bw + (size_t)(n0 + row) * K + k0 + ch * 8);
        }
    };

    float c[MF][NF][4];
    #pragma unroll
    for (int i = 0; i < MF; i++)
        #pragma unroll
        for (int jj = 0; jj < NF; jj++)
            #pragma unroll
            for (int q = 0; q < 4; q++) c[i][jj][q] = 0.0f;

    fill(0, 0);
    asm volatile("cp.async.commit_group;");

    for (int it = 0; it < NK; ++it) {
        if (it + 1 < NK) {
            fill((it + 1) & 1, (it + 1) * HBK);
            asm volatile("cp.async.commit_group;");
            asm volatile("cp.async.wait_group 1;");
        } else {
            asm volatile("cp.async.wait_group 0;");
        }
        __syncthreads();

        const int buf = it & 1;
        #pragma unroll
        for (int ks = 0; ks < 2; ks++) {
            const int k16 = ks * 16;
            uint32_t a[MF][4], b[NF][2];
            #pragma unroll
            for (int mf = 0; mf < MF; mf++)
                ldsm_x4(a[mf], as_base +
                    ((buf * BM + m_off + 16 * mf + a_row_lane) * HPITCH
                     + k16 + a_k_lane) * 2);
            #pragma unroll
            for (int nf = 0; nf < NF; nf++)
                ldsm_x2(b[nf][0], b[nf][1], bs_base +
                    ((buf * BN + n_off + 8 * nf + b_row_lane) * HPITCH
                     + k16 + b_k_lane) * 2);
            #pragma unroll
            for (int mf = 0; mf < MF; mf++)
                #pragma unroll
                for (int nf = 0; nf < NF; nf++)
                    asm volatile(
                        "mma.sync.aligned.m16n8k16.row.col.f32.f16.f16.f32 "
                        "{%0,%1,%2,%3}, {%4,%5,%6,%7}, {%8,%9}, {%0,%1,%2,%3};"
                        : "+f"(c[mf][nf][0]), "+f"(c[mf][nf][1]),
                          "+f"(c[mf][nf][2]), "+f"(c[mf][nf][3])
                        : "r"(a[mf][0]), "r"(a[mf][1]), "r"(a[mf][2]), "r"(a[mf][3]),
                          "r"(b[nf][0]), "r"(b[nf][1]));
        }
        __syncthreads();
    }

    #pragma unroll
    for (int nf = 0; nf < NF; nf++) {
        int col = n0 + n_off + 8 * nf + 2 * t;
        float bb0 = 0.0f, bb1 = 0.0f;
        if (bias) { bb0 = __ldg(bias + col); bb1 = __ldg(bias + col + 1); }
        #pragma unroll
        for (int mf = 0; mf < MF; mf++) {
            int row = m0 + m_off + 16 * mf + g;
            float2 v0 = make_float2(c[mf][nf][0] + bb0, c[mf][nf][1] + bb1);
            *(float2*)(C + (size_t)row * N + col) = v0;
            float2 v1 = make_float2(c[mf][nf][2] + bb0, c[mf][nf][3] + bb1);
            *(float2*)(C + (size_t)(row + 8) * N + col) = v1;
        }
    }
}

// ---------------- gather: uint4 loads, fp16 8-tap partial accumulation --------
__global__ void __launch_bounds__(256) gather_kernel(const __half* __restrict__ xh)
{
    __shared__ __half2 w2s [2][HH][SS];
    __shared__ __half2 fr2s[2][HH][SS];
    __shared__ int     i0s [2][HH][SS];   // row offsets in uint4 units (i*CC/8)
    __shared__ int     i1s [2][HH][SS];

    const int bl0 = blockIdx.x * 2;
    const int tid = threadIdx.x;

    #pragma unroll
    for (int idx = tid; idx < 2 * HH * SS; idx += 256) {
        // per (p,h,s) tap parameters — FROZEN strict unfused fp32
        int p = idx >> 8;
        int h = (idx >> 5) & 7;
        int s = idx & 31;
        int bl = bl0 + p;
        int l  = bl & (LL - 1);
        float freq  = g_freq [bl * HH + h];
        float phase = g_phase[bl * HH + h];
        float tap   = (float)(s - 16) + 0.5f;
        float offs  = __fadd_rn(phase, __fmul_rn(freq, tap));   // NO fma
        float pos   = __fadd_rn((float)l, offs);
        pos = fmaxf(pos, 0.0f);
        pos = fminf(pos, (float)(LL - 1));
        float i0f  = floorf(pos);
        float frac = __fsub_rn(pos, i0f);
        int i0 = (int)i0f;
        int i1 = min(i0 + 1, LL - 1);
        float tb = __fmul_rn(__fadd_rn(offs, 256.0f), 0.125f);
        int bin = (int)floorf(tb);
        bin = max(0, min(bin, KK - 1));
        w2s [p][h][s] = __float2half2_rn(g_kmat[((size_t)bl * HH + h) * KK + bin]);
        fr2s[p][h][s] = __float2half2_rn(frac);
        i0s [p][h][s] = i0 * (CC / 8);
        i1s [p][h][s] = i1 * (CC / 8);
    }
    __syncthreads();

    // 256 threads: warps 0-3 -> position 0, warps 4-7 -> position 1.
    const int p    = tid >> 7;
    const int bl   = bl0 + p;
    const int b    = bl >> 10;
    const int t128 = tid & 127;
    const int h    = t128 >> 4;        // 16 uint4 per head (128 ch)
    const int d8   = t128 & 15;
    const uint4* base = (const uint4*)(xh + (size_t)b * (LL * CC)) + h * (DD / 8) + d8;

    float accf[8];
    #pragma unroll
    for (int q = 0; q < 8; q++) accf[q] = 0.0f;

    const __half2 hzero = __float2half2_rn(0.0f);
    #pragma unroll
    for (int sg = 0; sg < 4; sg++) {          // 4 groups of 8 taps
        __half2 acch[4];
        #pragma unroll
        for (int q = 0; q < 4; q++) acch[q] = hzero;
        #pragma unroll
        for (int s4 = 0; s4 < 8; s4++) {
            int s = sg * 8 + s4;
            uint4 u0 = __ldg(base + i0s[p][h][s]);
            uint4 u1 = __ldg(base + i1s[p][h][s]);
            __half2 fr = fr2s[p][h][s];
            __half2 w2 = w2s [p][h][s];
            const uint32_t* p0 = &u0.x;
            const uint32_t* p1 = &u1.x;
            #pragma unroll
            for (int q = 0; q < 4; q++) {
                __half2 f0 = *(__half2*)&p0[q];
                __half2 f1 = *(__half2*)&p1[q];
                __half2 gh = __hfma2(fr, __hsub2(f1, f0), f0);
                acch[q] = __hfma2(w2, gh, acch[q]);
            }
        }
        #pragma unroll
        for (int q = 0; q < 4; q++) {         // fp32 spill per 8 taps
            float2 fq = __half22float2(acch[q]);
            accf[2 * q    ] += fq.x;
            accf[2 * q + 1] += fq.y;
        }
    }

    uint4 o;
    uint32_t* po = &o.x;
    #pragma unroll
    for (int q = 0; q < 4; q++) {
        __half2 oh = __floats2half2_rn(accf[2 * q], accf[2 * q + 1]);
        po[q] = *(uint32_t*)&oh;
    }
    ((uint4*)g_yh)[(size_t)bl * (CC / 8) + t128] = o;
}

// ---------------- launch -----------------------------------------------------
extern "C" void kernel_launch(void* const* d_in, const int* in_sizes, int n_in,
                              void* d_out, int out_size) {
    const float* x        = (const float*)d_in[0];
    const float* wave_w   = (const float*)d_in[1];
    const float* wave_b   = (const float*)d_in[2];
    const float* kernel_w = (const float*)d_in[3];
    const float* kernel_b = (const float*)d_in[4];
    const float* out_w    = (const float*)d_in[5];
    float* out = (float*)d_out;

    float *p_kmat;
    __half *p_xh, *p_yh, *p_wkh, *p_woh;
    cudaGetSymbolAddress((void**)&p_kmat, g_kmat);
    cudaGetSymbolAddress((void**)&p_xh,   g_xh);
    cudaGetSymbolAddress((void**)&p_yh,   g_yh);
    cudaGetSymbolAddress((void**)&p_wkh,  g_wkh);
    cudaGetSymbolAddress((void**)&p_woh,  g_woh);

    // side stream: wave only; overlaps ONLY the zero-smem convert kernel,
    // joined before the GEMM chain (R10 contention lesson).
    cudaStream_t s2;
    cudaEvent_t ev_fork, ev_wave;
    cudaStreamCreateWithFlags(&s2, cudaStreamNonBlocking);
    cudaEventCreateWithFlags(&ev_fork, cudaEventDisableTiming);
    cudaEventCreateWithFlags(&ev_wave, cudaEventDisableTiming);

    constexpr int WAVE_SMEM = (16 * CC + 16 * WPITCH) * 4;   // ~130 KB
    cudaFuncSetAttribute(wave_exact_kernel,
                         cudaFuncAttributeMaxDynamicSharedMemorySize, WAVE_SMEM);

    cudaEventRecord(ev_fork, 0);
    cudaStreamWaitEvent(s2, ev_fork, 0);
    wave_exact_kernel<<<BL / 16, 256, WAVE_SMEM, s2>>>(x, wave_w, wave_b);
    cudaEventRecord(ev_wave, s2);

    // main stream: fused converts (overlap wave), then join, then GEMM chain
    cvt_all_kernel<<<(N4_TOT + 255) / 256, 256>>>(
        x, kernel_w, out_w, (uint2*)p_xh, (uint2*)p_wkh, (uint2*)p_woh);
    cudaStreamWaitEvent(0, ev_wave, 0);
    gemm_f16_kernel<64, 128, 2, 4><<<dim3(HK / 128, BL / 64), 256>>>(
        p_xh, p_wkh, kernel_b, p_kmat, BL, HK, CC);
    gather_kernel<<<BL / 2, 256>>>(p_xh);
    gemm_f16_kernel<128, 128, 4, 2><<<dim3(CC / 128, BL / 128), 256>>>(
        p_yh, p_woh, nullptr, out, BL, CC, CC);

    (void)in_sizes; (void)n_in; (void)out_size;
}